// round 1
// baseline (speedup 1.0000x reference)
#include <cuda_runtime.h>
#include <cuda_bf16.h>
#include <math.h>

#define NN   20000
#define BB   2
#define TT   12
#define FIN  9
#define HH   64
#define EE   200000
#define ROWS (BB*NN)   // 40000

// ---------------- scratch (device globals; no allocations allowed) ----------
__device__ int   g_cnt[NN];
__device__ int   g_fill[NN];
__device__ int   g_ptr[NN+1];
__device__ float g_deginv[NN];
__device__ int   g_csr_src[EE];
__device__ float g_csr_w[EE];
__device__ float g_y1[ROWS*HH];
__device__ float g_agg[ROWS*HH];
__device__ float g_y2[ROWS*HH];
__device__ float g_t9[ROWS*FIN];
__device__ float g_xr9[ROWS*FIN];
__device__ float g_h[ROWS*FIN];
__device__ float g_outs[(long)BB*TT*NN*FIN];
__device__ float g_v[19];

// ---------------- setup kernels ---------------------------------------------
__global__ void zero_kernel() {
    int i = blockIdx.x * 256 + threadIdx.x;
    if (i < NN) { g_cnt[i] = 0; g_fill[i] = 0; }
    if (i < ROWS * FIN) g_h[i] = 0.f;
}

__global__ void count_kernel(const int* __restrict__ dst) {
    int e = blockIdx.x * 256 + threadIdx.x;
    if (e < EE) atomicAdd(&g_cnt[dst[e]], 1);
}

__global__ void __launch_bounds__(1024) scan_kernel() {
    __shared__ int sh[1024];
    __shared__ int carry;
    int tid = threadIdx.x;
    if (tid == 0) { carry = 0; g_ptr[0] = 0; }
    __syncthreads();
    for (int base = 0; base < NN; base += 1024) {
        int i = base + tid;
        int v = (i < NN) ? g_cnt[i] : 0;
        if (i < NN) g_deginv[i] = 1.0f / fmaxf((float)v, 1.0f);
        sh[tid] = v;
        __syncthreads();
        #pragma unroll
        for (int off = 1; off < 1024; off <<= 1) {
            int t = (tid >= off) ? sh[tid - off] : 0;
            __syncthreads();
            sh[tid] += t;
            __syncthreads();
        }
        if (i < NN) g_ptr[i + 1] = carry + sh[tid];
        __syncthreads();
        if (tid == 0) carry += sh[1023];
        __syncthreads();
    }
}

__global__ void fill_kernel(const int* __restrict__ src, const int* __restrict__ dst,
                            const float* __restrict__ w) {
    int e = blockIdx.x * 256 + threadIdx.x;
    if (e < EE) {
        int d = dst[e];
        int pos = g_ptr[d] + atomicAdd(&g_fill[d], 1);
        g_csr_src[pos] = src[e];
        g_csr_w[pos]   = w[e];
    }
}

// Collapse encoder+decoder (both linear, no activation between):
// out = x18 . v + c  where v[i] = sum_j encW[i][j]*decW[j], c = encb.decW + decb
__global__ void vprep_kernel(const float* __restrict__ encW, const float* __restrict__ encb,
                             const float* __restrict__ decW, const float* __restrict__ decb) {
    int i = threadIdx.x;
    if (i < 18) {
        float s = 0.f;
        for (int j = 0; j < 64; j++) s = fmaf(encW[i * 64 + j], decW[j], s);
        g_v[i] = s;
    } else if (i == 18) {
        float s = decb[0];
        for (int j = 0; j < 64; j++) s = fmaf(encb[j], decW[j], s);
        g_v[18] = s;
    }
}

// ---------------- per-timestep kernels --------------------------------------
__device__ __forceinline__ float elu_f(float v) { return v > 0.f ? v : expm1f(v); }

// y[row][f] = elu( a[row][:] @ Wl + x[row][:] @ Wr + bias )[f]
// DIN in {9, 64}, DOUT = 64. If AGG_FUSED: a is computed inline as CSR-mean of x.
// Block: 256 threads, 64 rows per block (4x4 register tile per thread).
template <int DIN, bool AGG_FUSED>
__global__ void __launch_bounds__(256) lin_kernel(
    const float* __restrict__ a,   // [b][n][DIN] contiguous (unused if AGG_FUSED)
    const float* __restrict__ x,   // base + b*x_bs + n*DIN + k
    long x_bs,
    const float* __restrict__ Wl, const float* __restrict__ Wr,
    const float* __restrict__ bias,
    float* __restrict__ y)
{
    constexpr int PAD = DIN + 1;
    extern __shared__ float smem[];
    float* sWl = smem;                    // DIN*64
    float* sWr = sWl + DIN * 64;          // DIN*64
    float* sb  = sWr + DIN * 64;          // 64
    float* sa  = sb + 64;                 // 64*PAD
    float* sx  = sa + 64 * PAD;           // 64*PAD

    int tid = threadIdx.x;
    for (int i = tid; i < DIN * 64; i += 256) { sWl[i] = Wl[i]; sWr[i] = Wr[i]; }
    if (tid < 64) sb[tid] = bias[tid];

    int row0 = blockIdx.x * 64;
    for (int i = tid; i < 64 * DIN; i += 256) {
        int rr = i / DIN, k = i % DIN;
        int row = row0 + rr;
        float av = 0.f, xv = 0.f;
        if (row < ROWS) {
            int b = row / NN, n = row % NN;
            const float* xb = x + (long)b * x_bs;
            xv = xb[(long)n * DIN + k];
            if (AGG_FUSED) {
                int s = g_ptr[n], e = g_ptr[n + 1];
                float acc = 0.f;
                for (int j = s; j < e; j++)
                    acc = fmaf(g_csr_w[j], xb[(long)g_csr_src[j] * DIN + k], acc);
                av = acc * g_deginv[n];
            } else {
                av = a[((long)b * NN + n) * DIN + k];
            }
        }
        sa[rr * PAD + k] = av;
        sx[rr * PAD + k] = xv;
    }
    __syncthreads();

    int tx = tid & 15, ty = tid >> 4;   // tx -> f tile (4 cols), ty -> row tile (4 rows)
    int f0 = tx * 4, r0 = ty * 4;
    float acc[4][4];
    #pragma unroll
    for (int i = 0; i < 4; i++)
        #pragma unroll
        for (int j = 0; j < 4; j++) acc[i][j] = sb[f0 + j];

    #pragma unroll 8
    for (int k = 0; k < DIN; k++) {
        float4 wl = *(const float4*)&sWl[k * 64 + f0];
        float4 wr = *(const float4*)&sWr[k * 64 + f0];
        #pragma unroll
        for (int i = 0; i < 4; i++) {
            float av = sa[(r0 + i) * PAD + k];
            float xv = sx[(r0 + i) * PAD + k];
            acc[i][0] = fmaf(av, wl.x, fmaf(xv, wr.x, acc[i][0]));
            acc[i][1] = fmaf(av, wl.y, fmaf(xv, wr.y, acc[i][1]));
            acc[i][2] = fmaf(av, wl.z, fmaf(xv, wr.z, acc[i][2]));
            acc[i][3] = fmaf(av, wl.w, fmaf(xv, wr.w, acc[i][3]));
        }
    }

    #pragma unroll
    for (int i = 0; i < 4; i++) {
        int row = row0 + r0 + i;
        if (row < ROWS) {
            #pragma unroll
            for (int j = 0; j < 4; j++)
                y[(long)row * 64 + f0 + j] = elu_f(acc[i][j]);
        }
    }
}

// agg64: out[b][n][f] = deginv[n] * sum_e w_e * x[b][src_e][f]   (f fastest -> coalesced)
__global__ void __launch_bounds__(256) agg64_kernel(const float* __restrict__ x,
                                                    float* __restrict__ out) {
    long i = (long)blockIdx.x * 256 + threadIdx.x;
    if (i >= (long)ROWS * 64) return;
    int f = (int)(i & 63);
    long rn = i >> 6;
    int b = (int)(rn / NN), n = (int)(rn % NN);
    int s = g_ptr[n], e = g_ptr[n + 1];
    const float* xb = x + (long)b * NN * 64;
    float acc = 0.f;
    for (int j = s; j < e; j++)
        acc = fmaf(g_csr_w[j], xb[((long)g_csr_src[j] << 6) + f], acc);
    out[i] = acc * g_deginv[n];
}

// pre3: t9 = y2 @ W3l ; xr9 = y2 @ W3r   (agg commutes with right-multiply:
// we aggregate t9 at d=9 instead of y2 at d=64)
__global__ void __launch_bounds__(256) pre3_kernel(const float* __restrict__ y2,
                                                   const float* __restrict__ W3l,
                                                   const float* __restrict__ W3r,
                                                   float* __restrict__ t9,
                                                   float* __restrict__ xr9) {
    __shared__ float sl[64 * 9], sr[64 * 9];
    int tid = threadIdx.x;
    for (int i = tid; i < 576; i += 256) { sl[i] = W3l[i]; sr[i] = W3r[i]; }
    __syncthreads();
    long idx = (long)blockIdx.x * 256 + tid;
    if (idx >= (long)ROWS * 9) return;
    int row = (int)(idx / 9), f = (int)(idx % 9);
    const float* yr = y2 + (long)row * 64;
    float al = 0.f, ar = 0.f;
    #pragma unroll 16
    for (int k = 0; k < 64; k++) {
        float v = yr[k];
        al = fmaf(v, sl[k * 9 + f], al);
        ar = fmaf(v, sr[k * 9 + f], ar);
    }
    t9[idx] = al;
    xr9[idx] = ar;
}

// fused: sage3 aggregation (d=9) + elu + GRU cell + write h and outs[t]
__global__ void __launch_bounds__(256) gru_kernel(const float* __restrict__ b3,
                                                  const float* __restrict__ Wih,
                                                  const float* __restrict__ Whh,
                                                  const float* __restrict__ bih,
                                                  const float* __restrict__ bhh,
                                                  int t) {
    __shared__ float swih[9 * 27], swhh[9 * 27], sb3[9], sbi[27], sbh[27];
    int tid = threadIdx.x;
    for (int i = tid; i < 243; i += 256) { swih[i] = Wih[i]; swhh[i] = Whh[i]; }
    if (tid < 27) { sbi[tid] = bih[tid]; sbh[tid] = bhh[tid]; }
    if (tid < 9) sb3[tid] = b3[tid];
    __syncthreads();

    int idx = blockIdx.x * 256 + tid;
    if (idx >= ROWS) return;
    int b = idx / NN, n = idx % NN;

    float agg[9];
    #pragma unroll
    for (int f = 0; f < 9; f++) agg[f] = 0.f;
    {
        int s = g_ptr[n], e = g_ptr[n + 1];
        const float* tb = g_t9 + (long)b * NN * 9;
        for (int j = s; j < e; j++) {
            float w = g_csr_w[j];
            const float* tp = tb + (long)g_csr_src[j] * 9;
            #pragma unroll
            for (int f = 0; f < 9; f++) agg[f] = fmaf(w, tp[f], agg[f]);
        }
    }
    float dinv = g_deginv[n];
    const float* xr = g_xr9 + (long)idx * 9;
    float y[9];
    #pragma unroll
    for (int f = 0; f < 9; f++) y[f] = elu_f(agg[f] * dinv + xr[f] + sb3[f]);

    float h[9];
    const float* hp = g_h + (long)idx * 9;
    #pragma unroll
    for (int f = 0; f < 9; f++) h[f] = hp[f];

    float gi[27], gh[27];
    #pragma unroll
    for (int j = 0; j < 27; j++) { gi[j] = sbi[j]; gh[j] = sbh[j]; }
    #pragma unroll
    for (int k = 0; k < 9; k++) {
        float yk = y[k], hk = h[k];
        #pragma unroll
        for (int j = 0; j < 27; j++) {
            gi[j] = fmaf(yk, swih[k * 27 + j], gi[j]);
            gh[j] = fmaf(hk, swhh[k * 27 + j], gh[j]);
        }
    }

    float* hw = g_h + (long)idx * 9;
    float* op = g_outs + (((long)b * TT + t) * NN + n) * 9;
    #pragma unroll
    for (int f = 0; f < 9; f++) {
        float r  = 1.f / (1.f + expf(-(gi[f] + gh[f])));
        float z  = 1.f / (1.f + expf(-(gi[9 + f] + gh[9 + f])));
        float nn = tanhf(gi[18 + f] + r * gh[18 + f]);
        float hv = (1.f - z) * nn + z * h[f];
        hw[f] = hv;
        op[f] = hv;
    }
}

// final collapsed encoder/decoder + mask
__global__ void __launch_bounds__(256) enc_kernel(const float* __restrict__ graph,
                                                  const float* __restrict__ tev,
                                                  float* __restrict__ out) {
    long i = (long)blockIdx.x * 256 + threadIdx.x;
    if (i >= (long)BB * TT * NN) return;
    int b = (int)(i / ((long)TT * NN));
    const float* o = g_outs + i * 9;
    float acc = g_v[18];
    #pragma unroll
    for (int f = 0; f < 9; f++) acc = fmaf(tev[b * 9 + f], g_v[9 + f], acc);
    #pragma unroll
    for (int f = 0; f < 9; f++) acc = fmaf(o[f], g_v[f], acc);
    out[i] = (graph[i * 9] != 0.f) ? acc : 0.f;
}

// ---------------- host ------------------------------------------------------
extern "C" void kernel_launch(void* const* d_in, const int* in_sizes, int n_in,
                              void* d_out, int out_size) {
    const float* graph = (const float*)d_in[0];
    const float* tev   = (const float*)d_in[1];
    // d_in[2] input_event: unused by the model
    const float* ew    = (const float*)d_in[3];
    const int*   esrc  = (const int*)d_in[4];
    const int*   edst  = (const int*)d_in[5];
    const float* W1l = (const float*)d_in[6];
    const float* b1  = (const float*)d_in[7];
    const float* W1r = (const float*)d_in[8];
    const float* W2l = (const float*)d_in[9];
    const float* b2  = (const float*)d_in[10];
    const float* W2r = (const float*)d_in[11];
    const float* W3l = (const float*)d_in[12];
    const float* b3  = (const float*)d_in[13];
    const float* W3r = (const float*)d_in[14];
    const float* Wih = (const float*)d_in[15];
    const float* Whh = (const float*)d_in[16];
    const float* bih = (const float*)d_in[17];
    const float* bhh = (const float*)d_in[18];
    const float* encW = (const float*)d_in[19];
    const float* encb = (const float*)d_in[20];
    const float* decW = (const float*)d_in[21];
    const float* decb = (const float*)d_in[22];
    float* out = (float*)d_out;

    float *p_y1, *p_agg, *p_y2, *p_t9, *p_xr9;
    cudaGetSymbolAddress((void**)&p_y1,  g_y1);
    cudaGetSymbolAddress((void**)&p_agg, g_agg);
    cudaGetSymbolAddress((void**)&p_y2,  g_y2);
    cudaGetSymbolAddress((void**)&p_t9,  g_t9);
    cudaGetSymbolAddress((void**)&p_xr9, g_xr9);

    const int smem9  = (2 * 9 * 64  + 64 + 2 * 64 * 10) * (int)sizeof(float);
    const int smem64 = (2 * 64 * 64 + 64 + 2 * 64 * 65) * (int)sizeof(float);
    cudaFuncSetAttribute(lin_kernel<64, false>,
                         cudaFuncAttributeMaxDynamicSharedMemorySize, smem64);

    zero_kernel<<<(ROWS * FIN + 255) / 256, 256>>>();
    count_kernel<<<(EE + 255) / 256, 256>>>(edst);
    scan_kernel<<<1, 1024>>>();
    fill_kernel<<<(EE + 255) / 256, 256>>>(esrc, edst, ew);
    vprep_kernel<<<1, 32>>>(encW, encb, decW, decb);

    const long xbs = (long)TT * NN * FIN;
    for (int t = 0; t < TT; t++) {
        const float* xt = graph + (long)t * NN * FIN;
        // sage1: fused CSR-mean agg (d=9) + 9->64 x2 GEMM + elu
        lin_kernel<9, true><<<625, 256, smem9>>>(
            nullptr, xt, xbs,
            W1l + t * 9 * 64, W1r + t * 9 * 64, b1 + t * 64, p_y1);
        // sage2 aggregation (d=64)
        agg64_kernel<<<((long)ROWS * 64 + 255) / 256, 256>>>(p_y1, p_agg);
        // sage2 linear: 64->64 x2 + elu
        lin_kernel<64, false><<<625, 256, smem64>>>(
            p_agg, p_y1, (long)NN * 64,
            W2l + t * 64 * 64, W2r + t * 64 * 64, b2 + t * 64, p_y2);
        // sage3 pre-multiply (agg commutes): t9 = y2@W3l, xr9 = y2@W3r
        pre3_kernel<<<((long)ROWS * 9 + 255) / 256, 256>>>(
            p_y2, W3l + t * 576, W3r + t * 576, p_t9, p_xr9);
        // sage3 agg(d=9) + elu + GRU fused
        gru_kernel<<<(ROWS + 255) / 256, 256>>>(
            b3 + t * 9, Wih + t * 243, Whh + t * 243,
            bih + t * 27, bhh + t * 27, t);
    }
    enc_kernel<<<((long)BB * TT * NN + 255) / 256, 256>>>(graph, tev, out);
}

// round 3
// speedup vs baseline: 1.0864x; 1.0864x over previous
#include <cuda_runtime.h>
#include <math.h>

#define NN   20000
#define BB   2
#define TT   12
#define FIN  9
#define HH   64
#define EE   200000
#define ROWS (BB*NN)   // 40000

#define GRU_BLOCKS ((ROWS + 255) / 256)   // 157
#define L9_BLOCKS  ((ROWS + 63) / 64)     // 625
#define K1_BLOCKS  ((ROWS + 127) / 128)   // 313

// ---------------- scratch (device globals; no allocations allowed) ----------
// __align__(16) is load-bearing: these are accessed through float4*.
__device__ int   g_cnt[NN];
__device__ int   g_fill[NN];
__device__ int   g_ptr[NN + 1];
__device__ float g_deginv[NN];
__device__ int   g_csr_src[EE];
__device__ float g_csr_w[EE];
__device__ __align__(16) float g_y1[ROWS * HH];
__device__ __align__(16) float g_t9[ROWS * FIN];
__device__ __align__(16) float g_xr9[ROWS * FIN];
__device__ __align__(16) float g_h[ROWS * FIN];
__device__ __align__(16) float g_outs[(long)BB * TT * NN * FIN];
__device__ float g_v[19];

// ---------------- setup kernels ---------------------------------------------
__global__ void zero_kernel() {
    int i = blockIdx.x * 256 + threadIdx.x;
    if (i < NN) { g_cnt[i] = 0; g_fill[i] = 0; }
    if (i < ROWS * FIN) g_h[i] = 0.f;
}

__global__ void count_kernel(const int* __restrict__ dst) {
    int e = blockIdx.x * 256 + threadIdx.x;
    if (e < EE) atomicAdd(&g_cnt[dst[e]], 1);
}

__global__ void __launch_bounds__(1024) scan_kernel() {
    __shared__ int sh[1024];
    __shared__ int carry;
    int tid = threadIdx.x;
    if (tid == 0) { carry = 0; g_ptr[0] = 0; }
    __syncthreads();
    for (int base = 0; base < NN; base += 1024) {
        int i = base + tid;
        int v = (i < NN) ? g_cnt[i] : 0;
        if (i < NN) g_deginv[i] = 1.0f / fmaxf((float)v, 1.0f);
        sh[tid] = v;
        __syncthreads();
        #pragma unroll
        for (int off = 1; off < 1024; off <<= 1) {
            int t = (tid >= off) ? sh[tid - off] : 0;
            __syncthreads();
            sh[tid] += t;
            __syncthreads();
        }
        if (i < NN) g_ptr[i + 1] = carry + sh[tid];
        __syncthreads();
        if (tid == 0) carry += sh[1023];
        __syncthreads();
    }
}

__global__ void fill_kernel(const int* __restrict__ src, const int* __restrict__ dst,
                            const float* __restrict__ w) {
    int e = blockIdx.x * 256 + threadIdx.x;
    if (e < EE) {
        int d = dst[e];
        int pos = g_ptr[d] + atomicAdd(&g_fill[d], 1);
        g_csr_src[pos] = src[e];
        g_csr_w[pos]   = w[e];
    }
}

// Collapse encoder+decoder (both linear, no activation between).
__global__ void vprep_kernel(const float* __restrict__ encW, const float* __restrict__ encb,
                             const float* __restrict__ decW, const float* __restrict__ decb) {
    int i = threadIdx.x;
    if (i < 18) {
        float s = 0.f;
        for (int j = 0; j < 64; j++) s = fmaf(encW[i * 64 + j], decW[j], s);
        g_v[i] = s;
    } else if (i == 18) {
        float s = decb[0];
        for (int j = 0; j < 64; j++) s = fmaf(encb[j], decW[j], s);
        g_v[18] = s;
    }
}

__device__ __forceinline__ float elu_f(float v) { return v > 0.f ? v : expm1f(v); }

// ============================================================================
// K1: fused sage2 — CSR-mean agg(d=64) of y1 + [agg|x] @ [W2l;W2r] (K=128)
//      + bias + elu, y2 kept in smem, epilogue computes t9 = y2@W3l and
//      xr9 = y2@W3r (agg commutes with right-multiply, done at d=9 in gru).
// 256 threads, 128 rows/block, per-thread 8x4 register tile.
// ============================================================================
#define SAX_STRIDE 132   // 128 + 4 pad (multiple of 4 floats -> float4-aligned rows)
#define SM64_FLOATS (8192 + 1152 + 64 + 128 * SAX_STRIDE)
#define SM64_BYTES  (SM64_FLOATS * 4)

__global__ void __launch_bounds__(256) lin64_kernel(
    const float* __restrict__ W2l, const float* __restrict__ W2r,
    const float* __restrict__ b2,
    const float* __restrict__ W3l, const float* __restrict__ W3r)
{
    extern __shared__ __align__(16) float sm[];
    float* sW  = sm;                 // [128][64] stacked Wl;Wr
    float* sW3 = sW + 8192;          // [2][64*9]
    float* sb  = sW3 + 1152;         // [64]
    float* sax = sb + 64;            // [128][SAX_STRIDE] : cols 0..63 agg, 64..127 x
                                     // base offset 9408 floats = 37632 B (16B-mult)

    int tid = threadIdx.x;
    for (int i = tid; i < 8192; i += 256)
        sW[i] = (i < 4096) ? W2l[i] : W2r[i - 4096];
    for (int i = tid; i < 1152; i += 256)
        sW3[i] = (i < 576) ? W3l[i] : W3r[i - 576];
    if (tid < 64) sb[tid] = b2[tid];

    int row0 = blockIdx.x * 128;
    int rr = tid >> 1, half = tid & 1;       // 2 threads per row, 32 k's each
    int row = row0 + rr;
    int off = half * 8;                      // float4 offset within row

    float4 a0, a1, a2, a3, a4, a5, a6, a7;
    a0 = a1 = a2 = a3 = a4 = a5 = a6 = a7 = make_float4(0.f, 0.f, 0.f, 0.f);
    float4 x0, x1, x2, x3, x4, x5, x6, x7;
    x0 = x1 = x2 = x3 = x4 = x5 = x6 = x7 = make_float4(0.f, 0.f, 0.f, 0.f);

    if (row < ROWS) {
        int b = row / NN, n = row % NN;
        const float4* xb = (const float4*)(g_y1 + (long)b * NN * 64);
        int s = g_ptr[n], e = g_ptr[n + 1];
        #pragma unroll 2
        for (int j = s; j < e; j++) {
            int src = g_csr_src[j];
            float w = g_csr_w[j];
            const float4* p = xb + src * 16 + off;
            float4 v;
            v = p[0]; a0.x = fmaf(w, v.x, a0.x); a0.y = fmaf(w, v.y, a0.y); a0.z = fmaf(w, v.z, a0.z); a0.w = fmaf(w, v.w, a0.w);
            v = p[1]; a1.x = fmaf(w, v.x, a1.x); a1.y = fmaf(w, v.y, a1.y); a1.z = fmaf(w, v.z, a1.z); a1.w = fmaf(w, v.w, a1.w);
            v = p[2]; a2.x = fmaf(w, v.x, a2.x); a2.y = fmaf(w, v.y, a2.y); a2.z = fmaf(w, v.z, a2.z); a2.w = fmaf(w, v.w, a2.w);
            v = p[3]; a3.x = fmaf(w, v.x, a3.x); a3.y = fmaf(w, v.y, a3.y); a3.z = fmaf(w, v.z, a3.z); a3.w = fmaf(w, v.w, a3.w);
            v = p[4]; a4.x = fmaf(w, v.x, a4.x); a4.y = fmaf(w, v.y, a4.y); a4.z = fmaf(w, v.z, a4.z); a4.w = fmaf(w, v.w, a4.w);
            v = p[5]; a5.x = fmaf(w, v.x, a5.x); a5.y = fmaf(w, v.y, a5.y); a5.z = fmaf(w, v.z, a5.z); a5.w = fmaf(w, v.w, a5.w);
            v = p[6]; a6.x = fmaf(w, v.x, a6.x); a6.y = fmaf(w, v.y, a6.y); a6.z = fmaf(w, v.z, a6.z); a6.w = fmaf(w, v.w, a6.w);
            v = p[7]; a7.x = fmaf(w, v.x, a7.x); a7.y = fmaf(w, v.y, a7.y); a7.z = fmaf(w, v.z, a7.z); a7.w = fmaf(w, v.w, a7.w);
        }
        float d = g_deginv[n];
        a0.x *= d; a0.y *= d; a0.z *= d; a0.w *= d;
        a1.x *= d; a1.y *= d; a1.z *= d; a1.w *= d;
        a2.x *= d; a2.y *= d; a2.z *= d; a2.w *= d;
        a3.x *= d; a3.y *= d; a3.z *= d; a3.w *= d;
        a4.x *= d; a4.y *= d; a4.z *= d; a4.w *= d;
        a5.x *= d; a5.y *= d; a5.z *= d; a5.w *= d;
        a6.x *= d; a6.y *= d; a6.z *= d; a6.w *= d;
        a7.x *= d; a7.y *= d; a7.z *= d; a7.w *= d;
        const float4* xr = xb + (long)n * 16 + off;
        x0 = xr[0]; x1 = xr[1]; x2 = xr[2]; x3 = xr[3];
        x4 = xr[4]; x5 = xr[5]; x6 = xr[6]; x7 = xr[7];
    }
    {
        float4* da = (float4*)(sax + rr * SAX_STRIDE) + half * 8;
        float4* dx = (float4*)(sax + rr * SAX_STRIDE + 64) + half * 8;
        da[0] = a0; da[1] = a1; da[2] = a2; da[3] = a3;
        da[4] = a4; da[5] = a5; da[6] = a6; da[7] = a7;
        dx[0] = x0; dx[1] = x1; dx[2] = x2; dx[3] = x3;
        dx[4] = x4; dx[5] = x5; dx[6] = x6; dx[7] = x7;
    }
    __syncthreads();

    // GEMM: 8 rows x 4 cols per thread, K=128
    int tx = tid & 15, ty = tid >> 4;
    int f0 = tx * 4, r0 = ty * 8;
    float4 acc[8];
    {
        float4 bv = *(const float4*)&sb[f0];
        #pragma unroll
        for (int i = 0; i < 8; i++) acc[i] = bv;
    }
    const float* wp = sW + f0;
    #pragma unroll 4
    for (int k = 0; k < 128; k += 4) {
        float4 w0 = *(const float4*)(wp + (k + 0) * 64);
        float4 w1 = *(const float4*)(wp + (k + 1) * 64);
        float4 w2 = *(const float4*)(wp + (k + 2) * 64);
        float4 w3 = *(const float4*)(wp + (k + 3) * 64);
        #pragma unroll
        for (int i = 0; i < 8; i++) {
            float4 a = *(const float4*)(sax + (r0 + i) * SAX_STRIDE + k);
            acc[i].x = fmaf(a.x, w0.x, fmaf(a.y, w1.x, fmaf(a.z, w2.x, fmaf(a.w, w3.x, acc[i].x))));
            acc[i].y = fmaf(a.x, w0.y, fmaf(a.y, w1.y, fmaf(a.z, w2.y, fmaf(a.w, w3.y, acc[i].y))));
            acc[i].z = fmaf(a.x, w0.z, fmaf(a.y, w1.z, fmaf(a.z, w2.z, fmaf(a.w, w3.z, acc[i].z))));
            acc[i].w = fmaf(a.x, w0.w, fmaf(a.y, w1.w, fmaf(a.z, w2.w, fmaf(a.w, w3.w, acc[i].w))));
        }
    }
    __syncthreads();   // all GEMM reads of sax complete

    // stash elu(y2) tile into sax cols 0..63
    #pragma unroll
    for (int i = 0; i < 8; i++) {
        float4 v = acc[i];
        v.x = elu_f(v.x); v.y = elu_f(v.y); v.z = elu_f(v.z); v.w = elu_f(v.w);
        *(float4*)(sax + (r0 + i) * SAX_STRIDE + f0) = v;
    }
    __syncthreads();

    // epilogue: t9 = y2 @ W3l, xr9 = y2 @ W3r  (per-thread: one row, one matrix)
    {
        int err2 = tid & 127;       // row within tile
        int m = tid >> 7;           // 0 -> t9, 1 -> xr9
        int grow = row0 + err2;
        const float* yrow = sax + err2 * SAX_STRIDE;
        const float* w3 = sW3 + m * 576;
        float o[9];
        #pragma unroll
        for (int f = 0; f < 9; f++) o[f] = 0.f;
        #pragma unroll 4
        for (int k = 0; k < 64; k++) {
            float v = yrow[k];
            const float* wk = w3 + k * 9;
            #pragma unroll
            for (int f = 0; f < 9; f++) o[f] = fmaf(v, wk[f], o[f]);
        }
        if (grow < ROWS) {
            float* dst = (m ? g_xr9 : g_t9) + (long)grow * 9;
            #pragma unroll
            for (int f = 0; f < 9; f++) dst[f] = o[f];
        }
    }
}

// ============================================================================
// Combo kernel: blocks [0, gru_blocks) run gru(t); the rest run lin9(t+1)
// (sage1: fused agg(d=9) + [agg|x] @ [W1l;W1r] (K=18) + elu -> g_y1).
// They are data-independent, so they co-schedule in one launch.
// ============================================================================
__global__ void __launch_bounds__(256) combo_kernel(
    int t, int gru_blocks,
    const float* __restrict__ graph,
    const float* __restrict__ W1l, const float* __restrict__ W1r,
    const float* __restrict__ b1,
    const float* __restrict__ b3,
    const float* __restrict__ Wih, const float* __restrict__ Whh,
    const float* __restrict__ bih, const float* __restrict__ bhh)
{
    int tid = threadIdx.x;
    if ((int)blockIdx.x < gru_blocks) {
        // ---------------- GRU(t): sage3 agg(d=9) + elu + GRU cell ----------
        __shared__ float swih[9 * 27], swhh[9 * 27], sb3[9], sbi[27], sbh[27];
        const float* wih = Wih + t * 243;
        const float* whh = Whh + t * 243;
        for (int i = tid; i < 243; i += 256) { swih[i] = wih[i]; swhh[i] = whh[i]; }
        if (tid < 27) { sbi[tid] = bih[t * 27 + tid]; sbh[tid] = bhh[t * 27 + tid]; }
        if (tid < 9) sb3[tid] = b3[t * 9 + tid];
        __syncthreads();

        int idx = blockIdx.x * 256 + tid;
        if (idx >= ROWS) return;
        int b = idx / NN, n = idx % NN;

        float agg[9];
        #pragma unroll
        for (int f = 0; f < 9; f++) agg[f] = 0.f;
        {
            int s = g_ptr[n], e = g_ptr[n + 1];
            const float* tb = g_t9 + (long)b * NN * 9;
            for (int j = s; j < e; j++) {
                float w = g_csr_w[j];
                const float* tp = tb + (long)g_csr_src[j] * 9;
                #pragma unroll
                for (int f = 0; f < 9; f++) agg[f] = fmaf(w, tp[f], agg[f]);
            }
        }
        float dinv = g_deginv[n];
        const float* xr = g_xr9 + (long)idx * 9;
        float y[9];
        #pragma unroll
        for (int f = 0; f < 9; f++) y[f] = elu_f(agg[f] * dinv + xr[f] + sb3[f]);

        float h[9];
        const float* hp = g_h + (long)idx * 9;
        #pragma unroll
        for (int f = 0; f < 9; f++) h[f] = hp[f];

        float gi[27], gh[27];
        #pragma unroll
        for (int j = 0; j < 27; j++) { gi[j] = sbi[j]; gh[j] = sbh[j]; }
        #pragma unroll
        for (int k = 0; k < 9; k++) {
            float yk = y[k], hk = h[k];
            #pragma unroll
            for (int j = 0; j < 27; j++) {
                gi[j] = fmaf(yk, swih[k * 27 + j], gi[j]);
                gh[j] = fmaf(hk, swhh[k * 27 + j], gh[j]);
            }
        }

        float* hw = g_h + (long)idx * 9;
        float* op = g_outs + (((long)b * TT + t) * NN + n) * 9;
        #pragma unroll
        for (int f = 0; f < 9; f++) {
            float r  = 1.f / (1.f + expf(-(gi[f] + gh[f])));
            float z  = 1.f / (1.f + expf(-(gi[9 + f] + gh[9 + f])));
            float nv = tanhf(gi[18 + f] + r * gh[18 + f]);
            float hv = (1.f - z) * nv + z * h[f];
            hw[f] = hv;
            op[f] = hv;
        }
    } else {
        // ---------------- lin9(t+1) --------------------------------------
        __shared__ __align__(16) float sW9[18 * 64];
        __shared__ __align__(16) float sb9[64];
        __shared__ float sax9[64 * 20];   // cols 0..8 agg, 9..17 x, stride 20

        int tn = t + 1;
        const float* w1l = W1l + tn * 576;
        const float* w1r = W1r + tn * 576;
        for (int i = tid; i < 1152; i += 256)
            sW9[i] = (i < 576) ? w1l[i] : w1r[i - 576];
        if (tid < 64) sb9[tid] = b1[tn * 64 + tid];

        int lb = blockIdx.x - gru_blocks;
        int row0 = lb * 64;
        const long xbs = (long)TT * NN * 9;
        const float* xt = graph + (long)tn * NN * 9;

        // x-copy
        for (int i = tid; i < 576; i += 256) {
            int rr = i / 9, f = i % 9;
            int row = row0 + rr;
            float v = 0.f;
            if (row < ROWS) {
                int b = row / NN, n = row % NN;
                v = xt[(long)b * xbs + (long)n * 9 + f];
            }
            sax9[rr * 20 + 9 + f] = v;
        }
        // gather (one thread per row)
        if (tid < 64) {
            int row = row0 + tid;
            float acc[9];
            #pragma unroll
            for (int f = 0; f < 9; f++) acc[f] = 0.f;
            float dinv = 0.f;
            if (row < ROWS) {
                int b = row / NN, n = row % NN;
                const float* xb = xt + (long)b * xbs;
                int s = g_ptr[n], e = g_ptr[n + 1];
                for (int j = s; j < e; j++) {
                    float w = g_csr_w[j];
                    const float* xp = xb + (long)g_csr_src[j] * 9;
                    #pragma unroll
                    for (int f = 0; f < 9; f++) acc[f] = fmaf(w, xp[f], acc[f]);
                }
                dinv = g_deginv[n];
            }
            #pragma unroll
            for (int f = 0; f < 9; f++) sax9[tid * 20 + f] = acc[f] * dinv;
        }
        __syncthreads();

        // GEMM: 4 rows x 4 cols per thread, K=18
        int tx = tid & 15, ty = tid >> 4;
        int f0 = tx * 4, r0 = ty * 4;
        float4 acc[4];
        {
            float4 bv = *(const float4*)&sb9[f0];
            #pragma unroll
            for (int i = 0; i < 4; i++) acc[i] = bv;
        }
        #pragma unroll
        for (int k = 0; k < 18; k++) {
            float4 w = *(const float4*)&sW9[k * 64 + f0];
            #pragma unroll
            for (int i = 0; i < 4; i++) {
                float a = sax9[(r0 + i) * 20 + k];
                acc[i].x = fmaf(a, w.x, acc[i].x);
                acc[i].y = fmaf(a, w.y, acc[i].y);
                acc[i].z = fmaf(a, w.z, acc[i].z);
                acc[i].w = fmaf(a, w.w, acc[i].w);
            }
        }
        #pragma unroll
        for (int i = 0; i < 4; i++) {
            int row = row0 + r0 + i;
            if (row < ROWS) {
                float4 v = acc[i];
                v.x = elu_f(v.x); v.y = elu_f(v.y); v.z = elu_f(v.z); v.w = elu_f(v.w);
                *(float4*)(g_y1 + (long)row * 64 + f0) = v;
            }
        }
    }
}

// final collapsed encoder/decoder + mask
__global__ void __launch_bounds__(256) enc_kernel(const float* __restrict__ graph,
                                                  const float* __restrict__ tev,
                                                  float* __restrict__ out) {
    long i = (long)blockIdx.x * 256 + threadIdx.x;
    if (i >= (long)BB * TT * NN) return;
    int b = (int)(i / ((long)TT * NN));
    const float* o = g_outs + i * 9;
    float acc = g_v[18];
    #pragma unroll
    for (int f = 0; f < 9; f++) acc = fmaf(tev[b * 9 + f], g_v[9 + f], acc);
    #pragma unroll
    for (int f = 0; f < 9; f++) acc = fmaf(o[f], g_v[f], acc);
    out[i] = (graph[i * 9] != 0.f) ? acc : 0.f;
}

// ---------------- host ------------------------------------------------------
extern "C" void kernel_launch(void* const* d_in, const int* in_sizes, int n_in,
                              void* d_out, int out_size) {
    const float* graph = (const float*)d_in[0];
    const float* tev   = (const float*)d_in[1];
    const float* ew    = (const float*)d_in[3];
    const int*   esrc  = (const int*)d_in[4];
    const int*   edst  = (const int*)d_in[5];
    const float* W1l = (const float*)d_in[6];
    const float* b1  = (const float*)d_in[7];
    const float* W1r = (const float*)d_in[8];
    const float* W2l = (const float*)d_in[9];
    const float* b2  = (const float*)d_in[10];
    const float* W2r = (const float*)d_in[11];
    const float* W3l = (const float*)d_in[12];
    const float* b3  = (const float*)d_in[13];
    const float* W3r = (const float*)d_in[14];
    const float* Wih = (const float*)d_in[15];
    const float* Whh = (const float*)d_in[16];
    const float* bih = (const float*)d_in[17];
    const float* bhh = (const float*)d_in[18];
    const float* encW = (const float*)d_in[19];
    const float* encb = (const float*)d_in[20];
    const float* decW = (const float*)d_in[21];
    const float* decb = (const float*)d_in[22];
    float* out = (float*)d_out;

    cudaFuncSetAttribute(lin64_kernel,
                         cudaFuncAttributeMaxDynamicSharedMemorySize, SM64_BYTES);

    zero_kernel<<<(ROWS * FIN + 255) / 256, 256>>>();
    count_kernel<<<(EE + 255) / 256, 256>>>(edst);
    scan_kernel<<<1, 1024>>>();
    fill_kernel<<<(EE + 255) / 256, 256>>>(esrc, edst, ew);
    vprep_kernel<<<1, 32>>>(encW, encb, decW, decb);

    for (int t = 0; t < TT; t++) {
        int gb = (t == 0) ? 0 : GRU_BLOCKS;
        // gru(t-1) [if t>0] + lin9(t) in one launch
        combo_kernel<<<gb + L9_BLOCKS, 256>>>(
            t - 1, gb, graph, W1l, W1r, b1, b3, Wih, Whh, bih, bhh);
        // fused sage2 + pre-multiplied sage3 projections
        lin64_kernel<<<K1_BLOCKS, 256, SM64_BYTES>>>(
            W2l + t * 4096, W2r + t * 4096, b2 + t * 64,
            W3l + t * 576, W3r + t * 576);
    }
    // final gru(11)
    combo_kernel<<<GRU_BLOCKS, 256>>>(
        11, GRU_BLOCKS, graph, W1l, W1r, b1, b3, Wih, Whh, bih, bhh);

    enc_kernel<<<((long)BB * TT * NN + 255) / 256, 256>>>(graph, tev, out);
}